// round 13
// baseline (speedup 1.0000x reference)
#include <cuda_runtime.h>
#include <cstdint>
#include <math.h>

// ---------------- problem constants ----------------
#define T_STEPS 512
#define BATCH   64
#define EMB_D   400
#define HID_D   1152
#define M_ROWS  (T_STEPS * BATCH)   // 32768

// ---------------- scratch (static device memory; no cudaMalloc allowed) ----
__device__ float g_act0[(size_t)M_ROWS * HID_D];
__device__ float g_act1[(size_t)M_ROWS * HID_D];
__device__ float g_xw[(size_t)M_ROWS * 4 * HID_D];
__device__ float g_h[2][HID_D * 128];        // DUPLICATED k-major hidden: [H][2*64], 2 bufs
__device__ unsigned int g_arrive;
__device__ unsigned int g_go;

// ---------------- packed f32x2 helpers ----------------
__device__ __forceinline__ unsigned long long pack2(float lo, float hi) {
    unsigned long long r;
    asm("mov.b64 %0, {%1, %2};" : "=l"(r) : "f"(lo), "f"(hi));
    return r;
}
__device__ __forceinline__ void unpack2(unsigned long long v, float& lo, float& hi) {
    asm("mov.b64 {%0, %1}, %2;" : "=f"(lo), "=f"(hi) : "l"(v));
}
__device__ __forceinline__ unsigned long long fma2(unsigned long long a,
                                                   unsigned long long b,
                                                   unsigned long long c) {
    unsigned long long d;
    asm("fma.rn.f32x2 %0, %1, %2, %3;" : "=l"(d) : "l"(a), "l"(b), "l"(c));
    return d;
}
__device__ __forceinline__ void cpasync16(uint32_t saddr, const float* g) {
    asm volatile("cp.async.cg.shared.global [%0], [%1], 16;" :: "r"(saddr), "l"(g));
}
__device__ __forceinline__ void cpcommit() {
    asm volatile("cp.async.commit_group;" ::: "memory");
}

// ---------------- misc helpers ----------------
__device__ __forceinline__ float sigm(float x) {
    return __fdividef(1.0f, 1.0f + __expf(-x));
}
__device__ __forceinline__ float tanh_f(float x) {
    return __fdividef(2.0f, 1.0f + __expf(-2.0f * x)) - 1.0f;
}

// barrier: atomic arrivals on g_arrive; LAST arriver publishes epoch to g_go;
// everyone else spins on the clean g_go line (no ping-pong with the atomics).
__device__ __forceinline__ void grid_barrier(int nctas, unsigned int ep) {
    __syncthreads();
    if (threadIdx.x == 0) {
        __threadfence();
        const unsigned int target = ep * (unsigned)nctas;
        unsigned int old = atomicAdd(&g_arrive, 1u);
        if (old + 1u == target) {
            asm volatile("st.release.gpu.u32 [%0], %1;" :: "l"(&g_go), "r"(ep) : "memory");
        } else {
            unsigned int v;
            do {
                asm volatile("ld.acquire.gpu.u32 %0, [%1];" : "=r"(v) : "l"(&g_go) : "memory");
            } while (v < ep);
        }
    }
    __syncthreads();
}

__global__ void reset_bar_kernel() { g_arrive = 0u; g_go = 0u; }

// ---------------- input projection: out[M][N] = A[M][K] @ W[N][K]^T + bias ----
// 256x128 tile, BK=16, 256 threads, 16m x 8n micro-tile, B-side duplication.
// Optional xidx: A row m = A + xidx[m]*K (fused embedding gather for layer 0).
__global__ void __launch_bounds__(256, 1)
gemm_xw3_kernel(const float* __restrict__ A, const float* __restrict__ W,
                const float* __restrict__ bih, const float* __restrict__ bhh,
                float* __restrict__ out, int N, int K, const int* __restrict__ xidx) {
    extern __shared__ float smg[];
    float* sAs = smg;                    // [2][16][256]
    float* sBs = smg + 2 * 16 * 256;     // [2][16][128]

    const int tid = threadIdx.x;
    const int tm  = tid & 15;
    const int tn  = tid >> 4;
    const int m0  = blockIdx.y * 256;
    const int n0  = blockIdx.x * 128;

    const float* Ap = xidx ? (A + (size_t)__ldg(xidx + m0 + tid) * K)
                           : (A + (size_t)(m0 + tid) * K);
    const int fst  = tid ^ ((tid >> 1) & 0x1C);
    const int bn   = tid >> 1;
    const int bkq  = (tid & 1) * 8;
    const float* Wp = W + (size_t)(n0 + bn) * K + bkq;
    const bool bok  = (n0 + bn) < N;

    int aoff[4];
#pragma unroll
    for (int j = 0; j < 4; ++j) {
        const int m = tm * 16 + j * 4;
        aoff[j] = m ^ ((m >> 1) & 0x1C);
    }

    const int NT = K / 16;

    unsigned long long acc[8][8];
#pragma unroll
    for (int mp = 0; mp < 8; ++mp)
#pragma unroll
        for (int n = 0; n < 8; ++n) acc[mp][n] = 0ull;

    const float4 z4 = make_float4(0.f, 0.f, 0.f, 0.f);
    float4 apf[4], bpf[2];

#pragma unroll
    for (int j = 0; j < 4; ++j) apf[j] = *(const float4*)(Ap + j * 4);
    bpf[0] = bok ? *(const float4*)(Wp)     : z4;
    bpf[1] = bok ? *(const float4*)(Wp + 4) : z4;
    {
        float* sa = sAs;
        float* sb = sBs;
#pragma unroll
        for (int j = 0; j < 4; ++j) {
            sa[(j * 4 + 0) * 256 + fst] = apf[j].x;
            sa[(j * 4 + 1) * 256 + fst] = apf[j].y;
            sa[(j * 4 + 2) * 256 + fst] = apf[j].z;
            sa[(j * 4 + 3) * 256 + fst] = apf[j].w;
        }
        sb[(bkq + 0) * 128 + bn] = bpf[0].x;
        sb[(bkq + 1) * 128 + bn] = bpf[0].y;
        sb[(bkq + 2) * 128 + bn] = bpf[0].z;
        sb[(bkq + 3) * 128 + bn] = bpf[0].w;
        sb[(bkq + 4) * 128 + bn] = bpf[1].x;
        sb[(bkq + 5) * 128 + bn] = bpf[1].y;
        sb[(bkq + 6) * 128 + bn] = bpf[1].z;
        sb[(bkq + 7) * 128 + bn] = bpf[1].w;
    }
    __syncthreads();

    for (int it = 0; it < NT; ++it) {
        const int nxt = it + 1;
        if (nxt < NT) {
            const float* ap2 = Ap + nxt * 16;
#pragma unroll
            for (int j = 0; j < 4; ++j) apf[j] = *(const float4*)(ap2 + j * 4);
            const float* wp2 = Wp + nxt * 16;
            bpf[0] = bok ? *(const float4*)(wp2)     : z4;
            bpf[1] = bok ? *(const float4*)(wp2 + 4) : z4;
        }
        {
            const float* sa = sAs + (it & 1) * (16 * 256);
            const float* sb = sBs + (it & 1) * (16 * 128);
#pragma unroll
            for (int k = 0; k < 16; ++k) {
                unsigned long long ra2[8];
#pragma unroll
                for (int j = 0; j < 4; ++j) {
                    const ulonglong2 q = *(const ulonglong2*)(sa + k * 256 + aoff[j]);
                    ra2[2 * j]     = q.x;
                    ra2[2 * j + 1] = q.y;
                }
                const float4 b0 = *(const float4*)(sb + k * 128 + tn * 8);
                const float4 b1 = *(const float4*)(sb + k * 128 + tn * 8 + 4);
                unsigned long long wb[8];
                wb[0] = pack2(b0.x, b0.x); wb[1] = pack2(b0.y, b0.y);
                wb[2] = pack2(b0.z, b0.z); wb[3] = pack2(b0.w, b0.w);
                wb[4] = pack2(b1.x, b1.x); wb[5] = pack2(b1.y, b1.y);
                wb[6] = pack2(b1.z, b1.z); wb[7] = pack2(b1.w, b1.w);
#pragma unroll
                for (int mp = 0; mp < 8; ++mp)
#pragma unroll
                    for (int n = 0; n < 8; ++n)
                        acc[mp][n] = fma2(ra2[mp], wb[n], acc[mp][n]);
            }
        }
        if (nxt < NT) {
            float* sa = sAs + (nxt & 1) * (16 * 256);
            float* sb = sBs + (nxt & 1) * (16 * 128);
#pragma unroll
            for (int j = 0; j < 4; ++j) {
                sa[(j * 4 + 0) * 256 + fst] = apf[j].x;
                sa[(j * 4 + 1) * 256 + fst] = apf[j].y;
                sa[(j * 4 + 2) * 256 + fst] = apf[j].z;
                sa[(j * 4 + 3) * 256 + fst] = apf[j].w;
            }
            sb[(bkq + 0) * 128 + bn] = bpf[0].x;
            sb[(bkq + 1) * 128 + bn] = bpf[0].y;
            sb[(bkq + 2) * 128 + bn] = bpf[0].z;
            sb[(bkq + 3) * 128 + bn] = bpf[0].w;
            sb[(bkq + 4) * 128 + bn] = bpf[1].x;
            sb[(bkq + 5) * 128 + bn] = bpf[1].y;
            sb[(bkq + 6) * 128 + bn] = bpf[1].z;
            sb[(bkq + 7) * 128 + bn] = bpf[1].w;
        }
        __syncthreads();
    }

    float bias[8];
#pragma unroll
    for (int jj = 0; jj < 8; ++jj) {
        const int n = n0 + tn * 8 + jj;
        bias[jj] = (n < N) ? (__ldg(bih + n) + __ldg(bhh + n)) : 0.0f;
    }
    const bool full = (n0 + 128 <= N);
#pragma unroll
    for (int mp = 0; mp < 8; ++mp) {
        float vlo[8], vhi[8];
#pragma unroll
        for (int n = 0; n < 8; ++n) unpack2(acc[mp][n], vlo[n], vhi[n]);
#pragma unroll
        for (int n = 0; n < 8; ++n) { vlo[n] += bias[n]; vhi[n] += bias[n]; }
        float* orow0 = out + (size_t)(m0 + tm * 16 + 2 * mp) * N + n0 + tn * 8;
        float* orow1 = out + (size_t)(m0 + tm * 16 + 2 * mp + 1) * N + n0 + tn * 8;
        if (full) {
            *(float4*)orow0       = make_float4(vlo[0], vlo[1], vlo[2], vlo[3]);
            *(float4*)(orow0 + 4) = make_float4(vlo[4], vlo[5], vlo[6], vlo[7]);
            *(float4*)orow1       = make_float4(vhi[0], vhi[1], vhi[2], vhi[3]);
            *(float4*)(orow1 + 4) = make_float4(vhi[4], vhi[5], vhi[6], vhi[7]);
        } else {
#pragma unroll
            for (int n = 0; n < 8; ++n)
                if (n0 + tn * 8 + n < N) { orow0[n] = vlo[n]; orow1[n] = vhi[n]; }
        }
    }
}

// ---------------- persistent recurrent LSTM layer (v7: duplicated-h) ----------
// g_h is [H][128] with every h value stored TWICE: staged SMEM pairs load as
// ready (h,h) u64 FFMA2 operands -> no pack2, no alu dep chain in inner loop.
// Chunks of 8 k (KS=144 = 18x8 exact). Per kk: 4+2 LDS.128 + 32 FFMA2.
// Stage buffer = 8 slices x 8 k x 128 dup = 8192 floats per buffer (FIXED stride).
template <int H>
__global__ void __launch_bounds__(256, 1)
lstm_rec7_kernel(const float* __restrict__ xw, const float* __restrict__ Whh,
                 float* __restrict__ out, int nctas) {
    constexpr int KS    = H / 8;                 // 144
    constexpr int NCH   = (KS + 7) / 8;          // 18
    constexpr int KPADZ = NCH * 8;               // 144
    constexpr int WFL   = 8 * KPADZ * 32;        // 36864
    constexpr int STAGEF = 8192;                 // floats per stage buffer

    extern __shared__ float sm[];
    float* sW     = sm;                          // [8z][KPADZ][32r]
    float* sStage = sW + WFL;                    // [2][STAGEF] = 16384 fl
    float* sC     = sStage;                      // alias: [8z][64b][32r] = 16384 fl
    float* sCell  = sStage + 16384;              // [512]

    const int tid  = threadIdx.x;
    const int z    = tid >> 5;
    const int lane = tid & 31;
    const int rgrp = lane & 3;
    const int bg   = lane >> 2;
    const int j0   = blockIdx.x * 8;

    for (int idx = tid; idx < WFL; idx += 256) {
        const int r  = idx & 31;
        const int kl = idx >> 5;
        const int zz = kl / KPADZ;
        const int kp = kl - zz * KPADZ;
        float v = 0.0f;
        if (kp < KS) {
            const int grow = (r >> 3) * H + j0 + (r & 7);
            v = Whh[(size_t)grow * H + zz * KS + kp];
        }
        sW[idx] = v;
    }
    for (int i = tid; i < 512; i += 256) {
        sCell[i] = 0.0f;
        const int u = i & 7, b = i >> 3;
        *(float2*)(&g_h[0][(j0 + u) * 128 + 2 * b]) = make_float2(0.f, 0.f);
    }
    unsigned int ep = 1;
    grid_barrier(nctas, ep); ++ep;

    const int c0b = tid >> 3, c0u = tid & 7;
    const int c1b = (tid + 256) >> 3, c1u = tid & 7;

    const uint32_t stage_s = (uint32_t)__cvta_generic_to_shared(sStage);
    const float* wbase = sW + z * KPADZ * 32;

    for (int t = 0; t < T_STEPS; ++t) {
        const float* hbuf = g_h[t & 1];
        float* hnext = g_h[1 - (t & 1)];

        float xwv[2][4];
        {
            const float* xb0 = xw + ((size_t)t * 64 + c0b) * (4 * H) + j0 + c0u;
            const float* xb1 = xw + ((size_t)t * 64 + c1b) * (4 * H) + j0 + c1u;
#pragma unroll
            for (int g = 0; g < 4; ++g) {
                xwv[0][g] = __ldg(xb0 + g * H);
                xwv[1][g] = __ldg(xb1 + g * H);
            }
        }

        // stage chunk 0: per slice 1024 floats (8k x 128 dup) = 256 float4
#pragma unroll
        for (int j = 0; j < 8; ++j)
            cpasync16(stage_s + (uint32_t)(j * 1024 + tid * 4) * 4,
                      hbuf + (j * KS) * 128 + tid * 4);
        cpcommit();

        unsigned long long acc[4][8];
#pragma unroll
        for (int rp = 0; rp < 4; ++rp)
#pragma unroll
            for (int b = 0; b < 8; ++b) acc[rp][b] = 0ull;

        for (int ci = 0; ci < NCH; ++ci) {
            if (ci + 1 < NCH) {
                const int buf = (ci + 1) & 1;
#pragma unroll
                for (int j = 0; j < 8; ++j)
                    cpasync16(stage_s + (uint32_t)(buf * STAGEF + j * 1024 + tid * 4) * 4,
                              hbuf + (j * KS + (ci + 1) * 8) * 128 + tid * 4);
                cpcommit();
                asm volatile("cp.async.wait_group 1;" ::: "memory");
            } else {
                asm volatile("cp.async.wait_group 0;" ::: "memory");
            }
            __syncthreads();

            const float* ab = sStage + (ci & 1) * STAGEF + z * 1024 + bg * 16;
            const ulonglong2* w2 = (const ulonglong2*)(wbase + ci * 8 * 32) + rgrp * 2;
#pragma unroll
            for (int kk = 0; kk < 8; ++kk) {
                const ulonglong2 q0 = *(const ulonglong2*)(ab + kk * 128);
                const ulonglong2 q1 = *(const ulonglong2*)(ab + kk * 128 + 4);
                const ulonglong2 q2 = *(const ulonglong2*)(ab + kk * 128 + 8);
                const ulonglong2 q3 = *(const ulonglong2*)(ab + kk * 128 + 12);
                const ulonglong2 wA = w2[kk * 8];
                const ulonglong2 wB = w2[kk * 8 + 1];
                acc[0][0] = fma2(wA.x, q0.x, acc[0][0]);
                acc[1][0] = fma2(wA.y, q0.x, acc[1][0]);
                acc[2][0] = fma2(wB.x, q0.x, acc[2][0]);
                acc[3][0] = fma2(wB.y, q0.x, acc[3][0]);
                acc[0][1] = fma2(wA.x, q0.y, acc[0][1]);
                acc[1][1] = fma2(wA.y, q0.y, acc[1][1]);
                acc[2][1] = fma2(wB.x, q0.y, acc[2][1]);
                acc[3][1] = fma2(wB.y, q0.y, acc[3][1]);
                acc[0][2] = fma2(wA.x, q1.x, acc[0][2]);
                acc[1][2] = fma2(wA.y, q1.x, acc[1][2]);
                acc[2][2] = fma2(wB.x, q1.x, acc[2][2]);
                acc[3][2] = fma2(wB.y, q1.x, acc[3][2]);
                acc[0][3] = fma2(wA.x, q1.y, acc[0][3]);
                acc[1][3] = fma2(wA.y, q1.y, acc[1][3]);
                acc[2][3] = fma2(wB.x, q1.y, acc[2][3]);
                acc[3][3] = fma2(wB.y, q1.y, acc[3][3]);
                acc[0][4] = fma2(wA.x, q2.x, acc[0][4]);
                acc[1][4] = fma2(wA.y, q2.x, acc[1][4]);
                acc[2][4] = fma2(wB.x, q2.x, acc[2][4]);
                acc[3][4] = fma2(wB.y, q2.x, acc[3][4]);
                acc[0][5] = fma2(wA.x, q2.y, acc[0][5]);
                acc[1][5] = fma2(wA.y, q2.y, acc[1][5]);
                acc[2][5] = fma2(wB.x, q2.y, acc[2][5]);
                acc[3][5] = fma2(wB.y, q2.y, acc[3][5]);
                acc[0][6] = fma2(wA.x, q3.x, acc[0][6]);
                acc[1][6] = fma2(wA.y, q3.x, acc[1][6]);
                acc[2][6] = fma2(wB.x, q3.x, acc[2][6]);
                acc[3][6] = fma2(wB.y, q3.x, acc[3][6]);
                acc[0][7] = fma2(wA.x, q3.y, acc[0][7]);
                acc[1][7] = fma2(wA.y, q3.y, acc[1][7]);
                acc[2][7] = fma2(wB.x, q3.y, acc[2][7]);
                acc[3][7] = fma2(wB.y, q3.y, acc[3][7]);
            }
        }
        __syncthreads();

#pragma unroll
        for (int b = 0; b < 8; ++b) {
            float* p = sC + z * 2048 + (bg * 8 + b) * 32 + rgrp * 8;
            *(ulonglong2*)p       = make_ulonglong2(acc[0][b], acc[1][b]);
            *(ulonglong2*)(p + 4) = make_ulonglong2(acc[2][b], acc[3][b]);
        }
        __syncthreads();

#pragma unroll
        for (int cc = 0; cc < 2; ++cc) {
            const int b = cc ? c1b : c0b;
            const int u = cc ? c1u : c0u;
            float gsum[4];
#pragma unroll
            for (int g = 0; g < 4; ++g) {
                const int o = b * 32 + g * 8 + u;
                float s = sC[o] + sC[2048 + o];
                s += sC[2 * 2048 + o] + sC[3 * 2048 + o];
                s += sC[4 * 2048 + o] + sC[5 * 2048 + o];
                s += sC[6 * 2048 + o] + sC[7 * 2048 + o];
                gsum[g] = s + xwv[cc][g];
            }
            const int cell = b * 8 + u;
            float c = sCell[cell];
            c = sigm(gsum[1]) * c + sigm(gsum[0]) * tanh_f(gsum[2]);
            sCell[cell] = c;
            const float hv = sigm(gsum[3]) * tanh_f(c);
            *(float2*)(hnext + (j0 + u) * 128 + 2 * b) = make_float2(hv, hv);
            out[((size_t)t * 64 + b) * H + j0 + u] = hv;
        }
        grid_barrier(nctas, ep); ++ep;
    }
}

// ---------------- layer-2 recurrence: NJ=4, H=400, duplicated-h ----------------
__global__ void __launch_bounds__(256, 1)
lstm_l2_kernel(const float* __restrict__ xw, const float* __restrict__ Whh,
               float* __restrict__ out, int nctas) {
    constexpr int H     = EMB_D;       // 400
    constexpr int KS    = H / 8;       // 50
    constexpr int NCH   = 7;           // ceil(50/8)
    constexpr int KPADZ = 56;
    constexpr int WFL   = 8 * KPADZ * 16;   // 7168 floats
    constexpr int STAGEF = 8192;            // floats per stage buffer

    extern __shared__ float sm[];
    float* sW     = sm;                     // [8z][56kp][16r]
    float* sStage = sW + WFL;               // [2][STAGEF] = 16384 fl
    float* sC     = sStage;                 // alias: [8z][64b][16r] = 8192 fl
    float* sCell  = sStage + 16384;         // [256]

    const int tid  = threadIdx.x;
    const int z    = tid >> 5;
    const int lane = tid & 31;
    const int rgrp = lane & 1;
    const int bg   = lane >> 1;
    const int j0   = blockIdx.x * 4;

    for (int idx = tid; idx < WFL; idx += 256) {
        const int r  = idx & 15;
        const int kl = idx >> 4;
        const int zz = kl / KPADZ;
        const int kp = kl - zz * KPADZ;
        float v = 0.0f;
        if (kp < KS) {
            const int grow = (r >> 2) * H + j0 + (r & 3);
            v = Whh[(size_t)grow * H + zz * KS + kp];
        }
        sW[idx] = v;
    }
    for (int i = tid; i < 256; i += 256) {
        sCell[i] = 0.0f;
        const int u = i & 3, b = i >> 2;
        *(float2*)(&g_h[0][(j0 + u) * 128 + 2 * b]) = make_float2(0.f, 0.f);
    }
    unsigned int ep = 1;
    grid_barrier(nctas, ep); ++ep;

    const int c0b = tid >> 2, c0u = tid & 3;

    const uint32_t stage_s = (uint32_t)__cvta_generic_to_shared(sStage);
    const float* wbase = sW + z * KPADZ * 16;

    for (int t = 0; t < T_STEPS; ++t) {
        const float* hbuf = g_h[t & 1];
        float* hnext = g_h[1 - (t & 1)];

        float xwv[4];
        {
            const float* xb0 = xw + ((size_t)t * 64 + c0b) * (4 * H) + j0 + c0u;
#pragma unroll
            for (int g = 0; g < 4; ++g) xwv[g] = __ldg(xb0 + g * H);
        }

        // over-read rows beyond H land inside g_h (sized HID_D*128) and meet zero W
#pragma unroll
        for (int j = 0; j < 8; ++j)
            cpasync16(stage_s + (uint32_t)(j * 1024 + tid * 4) * 4,
                      hbuf + (j * KS) * 128 + tid * 4);
        cpcommit();

        unsigned long long acc[4][4];
#pragma unroll
        for (int rp = 0; rp < 4; ++rp)
#pragma unroll
            for (int b = 0; b < 4; ++b) acc[rp][b] = 0ull;

        for (int ci = 0; ci < NCH; ++ci) {
            if (ci + 1 < NCH) {
                const int buf = (ci + 1) & 1;
#pragma unroll
                for (int j = 0; j < 8; ++j)
                    cpasync16(stage_s + (uint32_t)(buf * STAGEF + j * 1024 + tid * 4) * 4,
                              hbuf + (j * KS + (ci + 1) * 8) * 128 + tid * 4);
                cpcommit();
                asm volatile("cp.async.wait_group 1;" ::: "memory");
            } else {
                asm volatile("cp.async.wait_group 0;" ::: "memory");
            }
            __syncthreads();

            const float* ab = sStage + (ci & 1) * STAGEF + z * 1024 + bg * 8;
            const ulonglong2* w2 = (const ulonglong2*)(wbase + ci * 8 * 16) + rgrp * 2;
#pragma unroll
            for (int kk = 0; kk < 8; ++kk) {
                const ulonglong2 q0 = *(const ulonglong2*)(ab + kk * 128);
                const ulonglong2 q1 = *(const ulonglong2*)(ab + kk * 128 + 4);
                const ulonglong2 wA = w2[kk * 4];
                const ulonglong2 wB = w2[kk * 4 + 1];
                acc[0][0] = fma2(wA.x, q0.x, acc[0][0]);
                acc[1][0] = fma2(wA.y, q0.x, acc[1][0]);
                acc[2][0] = fma2(wB.x, q0.x, acc[2][0]);
                acc[3][0] = fma2(wB.y, q0.x, acc[3][0]);
                acc[0][1] = fma2(wA.x, q0.y, acc[0][1]);
                acc[1][1] = fma2(wA.y, q0.y, acc[1][1]);
                acc[2][1] = fma2(wB.x, q0.y, acc[2][1]);
                acc[3][1] = fma2(wB.y, q0.y, acc[3][1]);
                acc[0][2] = fma2(wA.x, q1.x, acc[0][2]);
                acc[1][2] = fma2(wA.y, q1.x, acc[1][2]);
                acc[2][2] = fma2(wB.x, q1.x, acc[2][2]);
                acc[3][2] = fma2(wB.y, q1.x, acc[3][2]);
                acc[0][3] = fma2(wA.x, q1.y, acc[0][3]);
                acc[1][3] = fma2(wA.y, q1.y, acc[1][3]);
                acc[2][3] = fma2(wB.x, q1.y, acc[2][3]);
                acc[3][3] = fma2(wB.y, q1.y, acc[3][3]);
            }
        }
        __syncthreads();

#pragma unroll
        for (int b = 0; b < 4; ++b) {
            float* p = sC + z * 1024 + (bg * 4 + b) * 16 + rgrp * 8;
            *(ulonglong2*)p       = make_ulonglong2(acc[0][b], acc[1][b]);
            *(ulonglong2*)(p + 4) = make_ulonglong2(acc[2][b], acc[3][b]);
        }
        __syncthreads();

        {
            const int b = c0b, u = c0u;
            float gsum[4];
#pragma unroll
            for (int g = 0; g < 4; ++g) {
                const int o = b * 16 + g * 4 + u;
                float s = sC[o] + sC[1024 + o];
                s += sC[2 * 1024 + o] + sC[3 * 1024 + o];
                s += sC[4 * 1024 + o] + sC[5 * 1024 + o];
                s += sC[6 * 1024 + o] + sC[7 * 1024 + o];
                gsum[g] = s + xwv[g];
            }
            float c = sCell[tid];
            c = sigm(gsum[1]) * c + sigm(gsum[0]) * tanh_f(gsum[2]);
            sCell[tid] = c;
            const float hv = sigm(gsum[3]) * tanh_f(c);
            *(float2*)(hnext + (j0 + u) * 128 + 2 * b) = make_float2(hv, hv);
            out[((size_t)t * 64 + b) * H + j0 + u] = hv;
        }
        grid_barrier(nctas, ep); ++ep;
    }
}

// ---------------- launch ----------------
extern "C" void kernel_launch(void* const* d_in, const int* in_sizes, int n_in,
                              void* d_out, int out_size) {
    (void)in_sizes; (void)n_in; (void)out_size;
    const int*   x    = (const int*)d_in[0];
    const float* emb  = (const float*)d_in[1];
    const float* Wih0 = (const float*)d_in[2];
    const float* Whh0 = (const float*)d_in[3];
    const float* bih0 = (const float*)d_in[4];
    const float* bhh0 = (const float*)d_in[5];
    const float* Wih1 = (const float*)d_in[6];
    const float* Whh1 = (const float*)d_in[7];
    const float* bih1 = (const float*)d_in[8];
    const float* bhh1 = (const float*)d_in[9];
    const float* Wih2 = (const float*)d_in[10];
    const float* Whh2 = (const float*)d_in[11];
    const float* bih2 = (const float*)d_in[12];
    const float* bhh2 = (const float*)d_in[13];
    float* out = (float*)d_out;

    float *act0, *act1, *xw;
    cudaGetSymbolAddress((void**)&act0, g_act0);
    cudaGetSymbolAddress((void**)&act1, g_act1);
    cudaGetSymbolAddress((void**)&xw, g_xw);

    const size_t SMEM_GEMM = (size_t)(2 * 16 * 256 + 2 * 16 * 128) * sizeof(float); // 49152
    const size_t SMEM_BIG  = (size_t)(8 * 144 * 32 + 16384 + 512) * sizeof(float);  // 215040
    const size_t SMEM_L2   = (size_t)(8 * 56 * 16 + 16384 + 256) * sizeof(float);   // 95232
    cudaFuncSetAttribute((const void*)gemm_xw3_kernel,
                         cudaFuncAttributeMaxDynamicSharedMemorySize, (int)SMEM_GEMM);
    cudaFuncSetAttribute((const void*)lstm_rec7_kernel<HID_D>,
                         cudaFuncAttributeMaxDynamicSharedMemorySize, (int)SMEM_BIG);
    cudaFuncSetAttribute((const void*)lstm_l2_kernel,
                         cudaFuncAttributeMaxDynamicSharedMemorySize, (int)SMEM_L2);

    // layer 0: din=400, H=1152 (embedding fused into the GEMM A-load)
    gemm_xw3_kernel<<<dim3(36, 128), 256, SMEM_GEMM>>>(emb, Wih0, bih0, bhh0, xw, 4 * HID_D, EMB_D, x);
    reset_bar_kernel<<<1, 1>>>();
    lstm_rec7_kernel<HID_D><<<144, 256, SMEM_BIG>>>(xw, Whh0, act1, 144);

    // layer 1: din=1152, H=1152
    gemm_xw3_kernel<<<dim3(36, 128), 256, SMEM_GEMM>>>(act1, Wih1, bih1, bhh1, xw, 4 * HID_D, HID_D, nullptr);
    reset_bar_kernel<<<1, 1>>>();
    lstm_rec7_kernel<HID_D><<<144, 256, SMEM_BIG>>>(xw, Whh1, act0, 144);

    // layer 2: din=1152, H=400 (100 CTAs, NJ=4)
    gemm_xw3_kernel<<<dim3(13, 128), 256, SMEM_GEMM>>>(act0, Wih2, bih2, bhh2, xw, 4 * EMB_D, HID_D, nullptr);
    reset_bar_kernel<<<1, 1>>>();
    lstm_l2_kernel<<<100, 256, SMEM_L2>>>(xw, Whh2, out, 100);
}

// round 14
// speedup vs baseline: 1.1805x; 1.1805x over previous
#include <cuda_runtime.h>
#include <cstdint>
#include <math.h>

// ---------------- problem constants ----------------
#define T_STEPS 512
#define BATCH   64
#define EMB_D   400
#define HID_D   1152
#define M_ROWS  (T_STEPS * BATCH)   // 32768

// ---------------- scratch (static device memory; no cudaMalloc allowed) ----
__device__ float g_act0[(size_t)M_ROWS * HID_D];
__device__ float g_act1[(size_t)M_ROWS * HID_D];
__device__ float g_xw[(size_t)M_ROWS * 4 * HID_D];
__device__ float g_h[2][BATCH * HID_D];      // k-major hidden: [H][64], 2 bufs
__device__ unsigned int g_arrive;
__device__ unsigned int g_go;

// ---------------- packed f32x2 helpers ----------------
__device__ __forceinline__ unsigned long long pack2(float lo, float hi) {
    unsigned long long r;
    asm("mov.b64 %0, {%1, %2};" : "=l"(r) : "f"(lo), "f"(hi));
    return r;
}
__device__ __forceinline__ void unpack2(unsigned long long v, float& lo, float& hi) {
    asm("mov.b64 {%0, %1}, %2;" : "=f"(lo), "=f"(hi) : "l"(v));
}
__device__ __forceinline__ unsigned long long fma2(unsigned long long a,
                                                   unsigned long long b,
                                                   unsigned long long c) {
    unsigned long long d;
    asm("fma.rn.f32x2 %0, %1, %2, %3;" : "=l"(d) : "l"(a), "l"(b), "l"(c));
    return d;
}
__device__ __forceinline__ void cpasync16(uint32_t saddr, const float* g) {
    asm volatile("cp.async.cg.shared.global [%0], [%1], 16;" :: "r"(saddr), "l"(g));
}
__device__ __forceinline__ void cpcommit() {
    asm volatile("cp.async.commit_group;" ::: "memory");
}

// ---------------- misc helpers ----------------
__device__ __forceinline__ float sigm(float x) {
    return __fdividef(1.0f, 1.0f + __expf(-x));
}
__device__ __forceinline__ float tanh_f(float x) {
    return __fdividef(2.0f, 1.0f + __expf(-2.0f * x)) - 1.0f;
}

// barrier: atomic arrivals on g_arrive; LAST arriver publishes epoch to g_go;
// everyone else spins on the clean g_go line.
__device__ __forceinline__ void grid_barrier(int nctas, unsigned int ep) {
    __syncthreads();
    if (threadIdx.x == 0) {
        __threadfence();
        const unsigned int target = ep * (unsigned)nctas;
        unsigned int old = atomicAdd(&g_arrive, 1u);
        if (old + 1u == target) {
            asm volatile("st.release.gpu.u32 [%0], %1;" :: "l"(&g_go), "r"(ep) : "memory");
        } else {
            unsigned int v;
            do {
                asm volatile("ld.acquire.gpu.u32 %0, [%1];" : "=r"(v) : "l"(&g_go) : "memory");
            } while (v < ep);
        }
    }
    __syncthreads();
}

__global__ void reset_bar_kernel() { g_arrive = 0u; g_go = 0u; }

// ---------------- input projection: out[M][N] = A[M][K] @ W[N][K]^T + bias ----
// 256x128 tile, BK=16, 256 threads, 16m x 8n micro-tile, B-side duplication.
// Optional xidx: A row m = A + xidx[m]*K (fused embedding gather for layer 0).
__global__ void __launch_bounds__(256, 1)
gemm_xw3_kernel(const float* __restrict__ A, const float* __restrict__ W,
                const float* __restrict__ bih, const float* __restrict__ bhh,
                float* __restrict__ out, int N, int K, const int* __restrict__ xidx) {
    extern __shared__ float smg[];
    float* sAs = smg;                    // [2][16][256]
    float* sBs = smg + 2 * 16 * 256;     // [2][16][128]

    const int tid = threadIdx.x;
    const int tm  = tid & 15;
    const int tn  = tid >> 4;
    const int m0  = blockIdx.y * 256;
    const int n0  = blockIdx.x * 128;

    const float* Ap = xidx ? (A + (size_t)__ldg(xidx + m0 + tid) * K)
                           : (A + (size_t)(m0 + tid) * K);
    const int fst  = tid ^ ((tid >> 1) & 0x1C);
    const int bn   = tid >> 1;
    const int bkq  = (tid & 1) * 8;
    const float* Wp = W + (size_t)(n0 + bn) * K + bkq;
    const bool bok  = (n0 + bn) < N;

    int aoff[4];
#pragma unroll
    for (int j = 0; j < 4; ++j) {
        const int m = tm * 16 + j * 4;
        aoff[j] = m ^ ((m >> 1) & 0x1C);
    }

    const int NT = K / 16;

    unsigned long long acc[8][8];
#pragma unroll
    for (int mp = 0; mp < 8; ++mp)
#pragma unroll
        for (int n = 0; n < 8; ++n) acc[mp][n] = 0ull;

    const float4 z4 = make_float4(0.f, 0.f, 0.f, 0.f);
    float4 apf[4], bpf[2];

#pragma unroll
    for (int j = 0; j < 4; ++j) apf[j] = *(const float4*)(Ap + j * 4);
    bpf[0] = bok ? *(const float4*)(Wp)     : z4;
    bpf[1] = bok ? *(const float4*)(Wp + 4) : z4;
    {
        float* sa = sAs;
        float* sb = sBs;
#pragma unroll
        for (int j = 0; j < 4; ++j) {
            sa[(j * 4 + 0) * 256 + fst] = apf[j].x;
            sa[(j * 4 + 1) * 256 + fst] = apf[j].y;
            sa[(j * 4 + 2) * 256 + fst] = apf[j].z;
            sa[(j * 4 + 3) * 256 + fst] = apf[j].w;
        }
        sb[(bkq + 0) * 128 + bn] = bpf[0].x;
        sb[(bkq + 1) * 128 + bn] = bpf[0].y;
        sb[(bkq + 2) * 128 + bn] = bpf[0].z;
        sb[(bkq + 3) * 128 + bn] = bpf[0].w;
        sb[(bkq + 4) * 128 + bn] = bpf[1].x;
        sb[(bkq + 5) * 128 + bn] = bpf[1].y;
        sb[(bkq + 6) * 128 + bn] = bpf[1].z;
        sb[(bkq + 7) * 128 + bn] = bpf[1].w;
    }
    __syncthreads();

    for (int it = 0; it < NT; ++it) {
        const int nxt = it + 1;
        if (nxt < NT) {
            const float* ap2 = Ap + nxt * 16;
#pragma unroll
            for (int j = 0; j < 4; ++j) apf[j] = *(const float4*)(ap2 + j * 4);
            const float* wp2 = Wp + nxt * 16;
            bpf[0] = bok ? *(const float4*)(wp2)     : z4;
            bpf[1] = bok ? *(const float4*)(wp2 + 4) : z4;
        }
        {
            const float* sa = sAs + (it & 1) * (16 * 256);
            const float* sb = sBs + (it & 1) * (16 * 128);
#pragma unroll
            for (int k = 0; k < 16; ++k) {
                unsigned long long ra2[8];
#pragma unroll
                for (int j = 0; j < 4; ++j) {
                    const ulonglong2 q = *(const ulonglong2*)(sa + k * 256 + aoff[j]);
                    ra2[2 * j]     = q.x;
                    ra2[2 * j + 1] = q.y;
                }
                const float4 b0 = *(const float4*)(sb + k * 128 + tn * 8);
                const float4 b1 = *(const float4*)(sb + k * 128 + tn * 8 + 4);
                unsigned long long wb[8];
                wb[0] = pack2(b0.x, b0.x); wb[1] = pack2(b0.y, b0.y);
                wb[2] = pack2(b0.z, b0.z); wb[3] = pack2(b0.w, b0.w);
                wb[4] = pack2(b1.x, b1.x); wb[5] = pack2(b1.y, b1.y);
                wb[6] = pack2(b1.z, b1.z); wb[7] = pack2(b1.w, b1.w);
#pragma unroll
                for (int mp = 0; mp < 8; ++mp)
#pragma unroll
                    for (int n = 0; n < 8; ++n)
                        acc[mp][n] = fma2(ra2[mp], wb[n], acc[mp][n]);
            }
        }
        if (nxt < NT) {
            float* sa = sAs + (nxt & 1) * (16 * 256);
            float* sb = sBs + (nxt & 1) * (16 * 128);
#pragma unroll
            for (int j = 0; j < 4; ++j) {
                sa[(j * 4 + 0) * 256 + fst] = apf[j].x;
                sa[(j * 4 + 1) * 256 + fst] = apf[j].y;
                sa[(j * 4 + 2) * 256 + fst] = apf[j].z;
                sa[(j * 4 + 3) * 256 + fst] = apf[j].w;
            }
            sb[(bkq + 0) * 128 + bn] = bpf[0].x;
            sb[(bkq + 1) * 128 + bn] = bpf[0].y;
            sb[(bkq + 2) * 128 + bn] = bpf[0].z;
            sb[(bkq + 3) * 128 + bn] = bpf[0].w;
            sb[(bkq + 4) * 128 + bn] = bpf[1].x;
            sb[(bkq + 5) * 128 + bn] = bpf[1].y;
            sb[(bkq + 6) * 128 + bn] = bpf[1].z;
            sb[(bkq + 7) * 128 + bn] = bpf[1].w;
        }
        __syncthreads();
    }

    float bias[8];
#pragma unroll
    for (int jj = 0; jj < 8; ++jj) {
        const int n = n0 + tn * 8 + jj;
        bias[jj] = (n < N) ? (__ldg(bih + n) + __ldg(bhh + n)) : 0.0f;
    }
    const bool full = (n0 + 128 <= N);
#pragma unroll
    for (int mp = 0; mp < 8; ++mp) {
        float vlo[8], vhi[8];
#pragma unroll
        for (int n = 0; n < 8; ++n) unpack2(acc[mp][n], vlo[n], vhi[n]);
#pragma unroll
        for (int n = 0; n < 8; ++n) { vlo[n] += bias[n]; vhi[n] += bias[n]; }
        float* orow0 = out + (size_t)(m0 + tm * 16 + 2 * mp) * N + n0 + tn * 8;
        float* orow1 = out + (size_t)(m0 + tm * 16 + 2 * mp + 1) * N + n0 + tn * 8;
        if (full) {
            *(float4*)orow0       = make_float4(vlo[0], vlo[1], vlo[2], vlo[3]);
            *(float4*)(orow0 + 4) = make_float4(vlo[4], vlo[5], vlo[6], vlo[7]);
            *(float4*)orow1       = make_float4(vhi[0], vhi[1], vhi[2], vhi[3]);
            *(float4*)(orow1 + 4) = make_float4(vhi[4], vhi[5], vhi[6], vhi[7]);
        } else {
#pragma unroll
            for (int n = 0; n < 8; ++n)
                if (n0 + tn * 8 + n < N) { orow0[n] = vlo[n]; orow1[n] = vhi[n]; }
        }
    }
}

// ---------------- persistent recurrent LSTM layer (v4 = 33.9ms config) ----------
template <int H>
__global__ void __launch_bounds__(256, 1)
lstm_rec4_kernel(const float* __restrict__ xw, const float* __restrict__ Whh,
                 float* __restrict__ out, int nctas) {
    constexpr int KS    = H / 8;
    constexpr int NCH   = (KS + 15) / 16;
    constexpr int KPADZ = NCH * 16;
    constexpr int WFL   = 8 * KPADZ * 32;

    extern __shared__ float sm[];
    float* sW     = sm;
    float* sStage = sW + WFL;                    // [2 buf][2048 float4] = 16384 fl
    float* sC     = sStage;
    float* sCell  = sStage + 16384;

    const int tid  = threadIdx.x;
    const int z    = tid >> 5;
    const int lane = tid & 31;
    const int rgrp = lane & 3;
    const int bg   = lane >> 2;
    const int j0   = blockIdx.x * 8;

    for (int idx = tid; idx < WFL; idx += 256) {
        const int r  = idx & 31;
        const int kl = idx >> 5;
        const int zz = kl / KPADZ;
        const int kp = kl - zz * KPADZ;
        float v = 0.0f;
        if (kp < KS) {
            const int grow = (r >> 3) * H + j0 + (r & 7);
            v = Whh[(size_t)grow * H + zz * KS + kp];
        }
        sW[idx] = v;
    }
    for (int i = tid; i < 512; i += 256) {
        sCell[i] = 0.0f;
        const int u = i & 7, b = i >> 3;
        g_h[0][(j0 + u) * 64 + b] = 0.0f;
    }
    unsigned int ep = 1;
    grid_barrier(nctas, ep); ++ep;

    const int c0b = tid >> 3, c0u = tid & 7;
    const int c1b = (tid + 256) >> 3, c1u = tid & 7;

    const uint32_t stage_s = (uint32_t)__cvta_generic_to_shared(sStage);
    const float* wbase = sW + z * KPADZ * 32;

    for (int t = 0; t < T_STEPS; ++t) {
        const float* hbuf = g_h[t & 1];
        float* hnext = g_h[1 - (t & 1)];

        float xwv[2][4];
        {
            const float* xb0 = xw + ((size_t)t * 64 + c0b) * (4 * H) + j0 + c0u;
            const float* xb1 = xw + ((size_t)t * 64 + c1b) * (4 * H) + j0 + c1u;
#pragma unroll
            for (int g = 0; g < 4; ++g) {
                xwv[0][g] = __ldg(xb0 + g * H);
                xwv[1][g] = __ldg(xb1 + g * H);
            }
        }

#pragma unroll
        for (int j = 0; j < 8; ++j)
            cpasync16(stage_s + (uint32_t)(j * 256 + tid) * 16,
                      hbuf + (j * KS) * 64 + tid * 4);
        cpcommit();

        unsigned long long acc[4][8];
#pragma unroll
        for (int rp = 0; rp < 4; ++rp)
#pragma unroll
            for (int b = 0; b < 8; ++b) acc[rp][b] = 0ull;

        for (int ci = 0; ci < NCH; ++ci) {
            if (ci + 1 < NCH) {
                const int buf = (ci + 1) & 1;
#pragma unroll
                for (int j = 0; j < 8; ++j)
                    cpasync16(stage_s + (uint32_t)(buf * 2048 + j * 256 + tid) * 16,
                              hbuf + (j * KS + (ci + 1) * 16) * 64 + tid * 4);
                cpcommit();
                asm volatile("cp.async.wait_group 1;" ::: "memory");
            } else {
                asm volatile("cp.async.wait_group 0;" ::: "memory");
            }
            __syncthreads();

            const float4* a4 = (const float4*)sStage + (ci & 1) * 2048 + z * 256;
            const ulonglong2* w2 = (const ulonglong2*)(wbase + ci * 16 * 32) + rgrp * 2;
#pragma unroll
            for (int kk = 0; kk < 16; ++kk) {
                const float4 h01 = a4[kk * 16 + bg * 2];
                const float4 h23 = a4[kk * 16 + bg * 2 + 1];
                const ulonglong2 wA = w2[kk * 8];
                const ulonglong2 wB = w2[kk * 8 + 1];
                const unsigned long long hp0 = pack2(h01.x, h01.x);
                const unsigned long long hp1 = pack2(h01.y, h01.y);
                const unsigned long long hp2 = pack2(h01.z, h01.z);
                const unsigned long long hp3 = pack2(h01.w, h01.w);
                const unsigned long long hp4 = pack2(h23.x, h23.x);
                const unsigned long long hp5 = pack2(h23.y, h23.y);
                const unsigned long long hp6 = pack2(h23.z, h23.z);
                const unsigned long long hp7 = pack2(h23.w, h23.w);
                acc[0][0] = fma2(wA.x, hp0, acc[0][0]);
                acc[1][0] = fma2(wA.y, hp0, acc[1][0]);
                acc[2][0] = fma2(wB.x, hp0, acc[2][0]);
                acc[3][0] = fma2(wB.y, hp0, acc[3][0]);
                acc[0][1] = fma2(wA.x, hp1, acc[0][1]);
                acc[1][1] = fma2(wA.y, hp1, acc[1][1]);
                acc[2][1] = fma2(wB.x, hp1, acc[2][1]);
                acc[3][1] = fma2(wB.y, hp1, acc[3][1]);
                acc[0][2] = fma2(wA.x, hp2, acc[0][2]);
                acc[1][2] = fma2(wA.y, hp2, acc[1][2]);
                acc[2][2] = fma2(wB.x, hp2, acc[2][2]);
                acc[3][2] = fma2(wB.y, hp2, acc[3][2]);
                acc[0][3] = fma2(wA.x, hp3, acc[0][3]);
                acc[1][3] = fma2(wA.y, hp3, acc[1][3]);
                acc[2][3] = fma2(wB.x, hp3, acc[2][3]);
                acc[3][3] = fma2(wB.y, hp3, acc[3][3]);
                acc[0][4] = fma2(wA.x, hp4, acc[0][4]);
                acc[1][4] = fma2(wA.y, hp4, acc[1][4]);
                acc[2][4] = fma2(wB.x, hp4, acc[2][4]);
                acc[3][4] = fma2(wB.y, hp4, acc[3][4]);
                acc[0][5] = fma2(wA.x, hp5, acc[0][5]);
                acc[1][5] = fma2(wA.y, hp5, acc[1][5]);
                acc[2][5] = fma2(wB.x, hp5, acc[2][5]);
                acc[3][5] = fma2(wB.y, hp5, acc[3][5]);
                acc[0][6] = fma2(wA.x, hp6, acc[0][6]);
                acc[1][6] = fma2(wA.y, hp6, acc[1][6]);
                acc[2][6] = fma2(wB.x, hp6, acc[2][6]);
                acc[3][6] = fma2(wB.y, hp6, acc[3][6]);
                acc[0][7] = fma2(wA.x, hp7, acc[0][7]);
                acc[1][7] = fma2(wA.y, hp7, acc[1][7]);
                acc[2][7] = fma2(wB.x, hp7, acc[2][7]);
                acc[3][7] = fma2(wB.y, hp7, acc[3][7]);
            }
        }
        __syncthreads();

#pragma unroll
        for (int b = 0; b < 8; ++b) {
            float* p = sC + z * 2048 + (bg * 8 + b) * 32 + rgrp * 8;
            *(ulonglong2*)p       = make_ulonglong2(acc[0][b], acc[1][b]);
            *(ulonglong2*)(p + 4) = make_ulonglong2(acc[2][b], acc[3][b]);
        }
        __syncthreads();

#pragma unroll
        for (int cc = 0; cc < 2; ++cc) {
            const int b = cc ? c1b : c0b;
            const int u = cc ? c1u : c0u;
            float gsum[4];
#pragma unroll
            for (int g = 0; g < 4; ++g) {
                const int o = b * 32 + g * 8 + u;
                float s = sC[o] + sC[2048 + o];
                s += sC[2 * 2048 + o] + sC[3 * 2048 + o];
                s += sC[4 * 2048 + o] + sC[5 * 2048 + o];
                s += sC[6 * 2048 + o] + sC[7 * 2048 + o];
                gsum[g] = s + xwv[cc][g];
            }
            const int cell = b * 8 + u;
            float c = sCell[cell];
            c = sigm(gsum[1]) * c + sigm(gsum[0]) * tanh_f(gsum[2]);
            sCell[cell] = c;
            const float hv = sigm(gsum[3]) * tanh_f(c);
            hnext[(j0 + u) * 64 + b] = hv;
            out[((size_t)t * 64 + b) * H + j0 + u] = hv;
        }
        grid_barrier(nctas, ep); ++ep;
    }
}

// ---------------- layer-2 recurrence: NJ=4, H=400 -> 100 CTAs (r11 config) ------
__global__ void __launch_bounds__(256, 1)
lstm_l2_kernel(const float* __restrict__ xw, const float* __restrict__ Whh,
               float* __restrict__ out, int nctas) {
    constexpr int H     = EMB_D;       // 400
    constexpr int KS    = H / 8;       // 50
    constexpr int NCH   = 4;           // ceil(50/16)
    constexpr int KPADZ = 64;
    constexpr int WFL   = 8 * KPADZ * 16;   // 8192 floats

    extern __shared__ float sm[];
    float* sW     = sm;                     // [8 z][64 kp][16 r]
    float* sStage = sW + WFL;               // [2][2048 float4] = 16384 fl
    float* sC     = sStage;                 // alias: [8 z][64 b][16 r] = 8192 fl
    float* sCell  = sStage + 16384;         // [256]

    const int tid  = threadIdx.x;
    const int z    = tid >> 5;
    const int lane = tid & 31;
    const int rgrp = lane & 1;
    const int bg   = lane >> 1;
    const int j0   = blockIdx.x * 4;

    for (int idx = tid; idx < WFL; idx += 256) {
        const int r  = idx & 15;
        const int kl = idx >> 4;
        const int zz = kl >> 6;
        const int kp = kl & 63;
        float v = 0.0f;
        if (kp < KS) {
            const int grow = (r >> 2) * H + j0 + (r & 3);
            v = Whh[(size_t)grow * H + zz * KS + kp];
        }
        sW[idx] = v;
    }
    for (int i = tid; i < 256; i += 256) {
        sCell[i] = 0.0f;
        const int u = i & 3, b = i >> 2;
        g_h[0][(j0 + u) * 64 + b] = 0.0f;
    }
    unsigned int ep = 1;
    grid_barrier(nctas, ep); ++ep;

    const int c0b = tid >> 2, c0u = tid & 3;

    const uint32_t stage_s = (uint32_t)__cvta_generic_to_shared(sStage);
    const float* wbase = sW + z * KPADZ * 16;

    for (int t = 0; t < T_STEPS; ++t) {
        const float* hbuf = g_h[t & 1];
        float* hnext = g_h[1 - (t & 1)];

        float xwv[4];
        {
            const float* xb0 = xw + ((size_t)t * 64 + c0b) * (4 * H) + j0 + c0u;
#pragma unroll
            for (int g = 0; g < 4; ++g) xwv[g] = __ldg(xb0 + g * H);
        }

#pragma unroll
        for (int j = 0; j < 8; ++j)
            cpasync16(stage_s + (uint32_t)(j * 256 + tid) * 16,
                      hbuf + (j * KS) * 64 + tid * 4);
        cpcommit();

        unsigned long long acc[4][4];
#pragma unroll
        for (int rp = 0; rp < 4; ++rp)
#pragma unroll
            for (int b = 0; b < 4; ++b) acc[rp][b] = 0ull;

        for (int ci = 0; ci < NCH; ++ci) {
            if (ci + 1 < NCH) {
                const int buf = (ci + 1) & 1;
#pragma unroll
                for (int j = 0; j < 8; ++j)
                    cpasync16(stage_s + (uint32_t)(buf * 2048 + j * 256 + tid) * 16,
                              hbuf + (j * KS + (ci + 1) * 16) * 64 + tid * 4);
                cpcommit();
                asm volatile("cp.async.wait_group 1;" ::: "memory");
            } else {
                asm volatile("cp.async.wait_group 0;" ::: "memory");
            }
            __syncthreads();

            const float4* a4 = (const float4*)sStage + (ci & 1) * 2048 + z * 256;
            const ulonglong2* w2 = (const ulonglong2*)(wbase + ci * 16 * 16) + rgrp * 2;
#pragma unroll
            for (int kk = 0; kk < 16; ++kk) {
                const float4 hq = a4[kk * 16 + bg];
                const ulonglong2 wA = w2[kk * 4];
                const ulonglong2 wB = w2[kk * 4 + 1];
                const unsigned long long hp0 = pack2(hq.x, hq.x);
                const unsigned long long hp1 = pack2(hq.y, hq.y);
                const unsigned long long hp2 = pack2(hq.z, hq.z);
                const unsigned long long hp3 = pack2(hq.w, hq.w);
                acc[0][0] = fma2(wA.x, hp0, acc[0][0]);
                acc[1][0] = fma2(wA.y, hp0, acc[1][0]);
                acc[2][0] = fma2(wB.x, hp0, acc[2][0]);
                acc[3][0] = fma2(wB.y, hp0, acc[3][0]);
                acc[0][1] = fma2(wA.x, hp1, acc[0][1]);
                acc[1][1] = fma2(wA.y, hp1, acc[1][1]);
                acc[2][1] = fma2(wB.x, hp1, acc[2][1]);
                acc[3][1] = fma2(wB.y, hp1, acc[3][1]);
                acc[0][2] = fma2(wA.x, hp2, acc[0][2]);
                acc[1][2] = fma2(wA.y, hp2, acc[1][2]);
                acc[2][2] = fma2(wB.x, hp2, acc[2][2]);
                acc[3][2] = fma2(wB.y, hp2, acc[3][2]);
                acc[0][3] = fma2(wA.x, hp3, acc[0][3]);
                acc[1][3] = fma2(wA.y, hp3, acc[1][3]);
                acc[2][3] = fma2(wB.x, hp3, acc[2][3]);
                acc[3][3] = fma2(wB.y, hp3, acc[3][3]);
            }
        }
        __syncthreads();

#pragma unroll
        for (int b = 0; b < 4; ++b) {
            float* p = sC + z * 1024 + (bg * 4 + b) * 16 + rgrp * 8;
            *(ulonglong2*)p       = make_ulonglong2(acc[0][b], acc[1][b]);
            *(ulonglong2*)(p + 4) = make_ulonglong2(acc[2][b], acc[3][b]);
        }
        __syncthreads();

        {
            const int b = c0b, u = c0u;
            float gsum[4];
#pragma unroll
            for (int g = 0; g < 4; ++g) {
                const int o = b * 16 + g * 4 + u;
                float s = sC[o] + sC[1024 + o];
                s += sC[2 * 1024 + o] + sC[3 * 1024 + o];
                s += sC[4 * 1024 + o] + sC[5 * 1024 + o];
                s += sC[6 * 1024 + o] + sC[7 * 1024 + o];
                gsum[g] = s + xwv[g];
            }
            float c = sCell[tid];
            c = sigm(gsum[1]) * c + sigm(gsum[0]) * tanh_f(gsum[2]);
            sCell[tid] = c;
            const float hv = sigm(gsum[3]) * tanh_f(c);
            hnext[(j0 + u) * 64 + b] = hv;
            out[((size_t)t * 64 + b) * H + j0 + u] = hv;
        }
        grid_barrier(nctas, ep); ++ep;
    }
}

// ---------------- launch ----------------
extern "C" void kernel_launch(void* const* d_in, const int* in_sizes, int n_in,
                              void* d_out, int out_size) {
    (void)in_sizes; (void)n_in; (void)out_size;
    const int*   x    = (const int*)d_in[0];
    const float* emb  = (const float*)d_in[1];
    const float* Wih0 = (const float*)d_in[2];
    const float* Whh0 = (const float*)d_in[3];
    const float* bih0 = (const float*)d_in[4];
    const float* bhh0 = (const float*)d_in[5];
    const float* Wih1 = (const float*)d_in[6];
    const float* Whh1 = (const float*)d_in[7];
    const float* bih1 = (const float*)d_in[8];
    const float* bhh1 = (const float*)d_in[9];
    const float* Wih2 = (const float*)d_in[10];
    const float* Whh2 = (const float*)d_in[11];
    const float* bih2 = (const float*)d_in[12];
    const float* bhh2 = (const float*)d_in[13];
    float* out = (float*)d_out;

    float *act0, *act1, *xw;
    cudaGetSymbolAddress((void**)&act0, g_act0);
    cudaGetSymbolAddress((void**)&act1, g_act1);
    cudaGetSymbolAddress((void**)&xw, g_xw);

    const size_t SMEM_GEMM = (size_t)(2 * 16 * 256 + 2 * 16 * 128) * sizeof(float); // 49152
    const size_t SMEM_BIG  = (size_t)(8 * 144 * 32 + 16384 + 512) * sizeof(float);  // 215040
    const size_t SMEM_L2   = (size_t)(8 * 64 * 16 + 16384 + 256) * sizeof(float);   // 99328
    cudaFuncSetAttribute((const void*)gemm_xw3_kernel,
                         cudaFuncAttributeMaxDynamicSharedMemorySize, (int)SMEM_GEMM);
    cudaFuncSetAttribute((const void*)lstm_rec4_kernel<HID_D>,
                         cudaFuncAttributeMaxDynamicSharedMemorySize, (int)SMEM_BIG);
    cudaFuncSetAttribute((const void*)lstm_l2_kernel,
                         cudaFuncAttributeMaxDynamicSharedMemorySize, (int)SMEM_L2);

    // layer 0: din=400, H=1152 (embedding fused into the GEMM A-load)
    gemm_xw3_kernel<<<dim3(36, 128), 256, SMEM_GEMM>>>(emb, Wih0, bih0, bhh0, xw, 4 * HID_D, EMB_D, x);
    reset_bar_kernel<<<1, 1>>>();
    lstm_rec4_kernel<HID_D><<<144, 256, SMEM_BIG>>>(xw, Whh0, act1, 144);

    // layer 1: din=1152, H=1152
    gemm_xw3_kernel<<<dim3(36, 128), 256, SMEM_GEMM>>>(act1, Wih1, bih1, bhh1, xw, 4 * HID_D, HID_D, nullptr);
    reset_bar_kernel<<<1, 1>>>();
    lstm_rec4_kernel<HID_D><<<144, 256, SMEM_BIG>>>(xw, Whh1, act0, 144);

    // layer 2: din=1152, H=400 (100 CTAs, NJ=4)
    gemm_xw3_kernel<<<dim3(13, 128), 256, SMEM_GEMM>>>(act0, Wih2, bih2, bhh2, xw, 4 * EMB_D, HID_D, nullptr);
    reset_bar_kernel<<<1, 1>>>();
    lstm_l2_kernel<<<100, 256, SMEM_L2>>>(xw, Whh2, out, 100);
}

// round 15
// speedup vs baseline: 1.2230x; 1.0360x over previous
#include <cuda_runtime.h>
#include <cstdint>
#include <math.h>

// ---------------- problem constants ----------------
#define T_STEPS 512
#define BATCH   64
#define EMB_D   400
#define HID_D   1152
#define M_ROWS  (T_STEPS * BATCH)   // 32768

// ---------------- scratch (static device memory; no cudaMalloc allowed) ----
__device__ float g_act0[(size_t)M_ROWS * HID_D];
__device__ float g_act1[(size_t)M_ROWS * HID_D];
__device__ float g_xw[(size_t)M_ROWS * 4 * HID_D];
__device__ float g_h[2][BATCH * HID_D];                 // k-major hidden: [H][64], 2 bufs
__device__ unsigned int g_arrive;

// ---------------- packed f32x2 helpers ----------------
__device__ __forceinline__ unsigned long long pack2(float lo, float hi) {
    unsigned long long r;
    asm("mov.b64 %0, {%1, %2};" : "=l"(r) : "f"(lo), "f"(hi));
    return r;
}
__device__ __forceinline__ void unpack2(unsigned long long v, float& lo, float& hi) {
    asm("mov.b64 {%0, %1}, %2;" : "=f"(lo), "=f"(hi) : "l"(v));
}
__device__ __forceinline__ unsigned long long fma2(unsigned long long a,
                                                   unsigned long long b,
                                                   unsigned long long c) {
    unsigned long long d;
    asm("fma.rn.f32x2 %0, %1, %2, %3;" : "=l"(d) : "l"(a), "l"(b), "l"(c));
    return d;
}
__device__ __forceinline__ void cpasync16(uint32_t saddr, const float* g) {
    asm volatile("cp.async.cg.shared.global [%0], [%1], 16;" :: "r"(saddr), "l"(g));
}
__device__ __forceinline__ void cpcommit() {
    asm volatile("cp.async.commit_group;" ::: "memory");
}

// ---------------- misc helpers ----------------
// FAST gates (only change vs the 33.9ms round-11 kernel): MUFU-based exp/div.
__device__ __forceinline__ float sigm(float x) {
    return __fdividef(1.0f, 1.0f + __expf(-x));
}
__device__ __forceinline__ float tanh_f(float x) {
    return __fdividef(2.0f, 1.0f + __expf(-2.0f * x)) - 1.0f;
}

__device__ __forceinline__ void grid_barrier(int nctas, unsigned int target) {
    __syncthreads();
    if (threadIdx.x == 0) {
        __threadfence();
        atomicAdd(&g_arrive, 1u);
        unsigned int v;
        do {
            asm volatile("ld.acquire.gpu.u32 %0, [%1];" : "=r"(v) : "l"(&g_arrive) : "memory");
        } while (v < target);
    }
    __syncthreads();
}

__global__ void reset_bar_kernel() { g_arrive = 0u; }

// ---------------- embedding gather ----------------
__global__ void embed_kernel(const int* __restrict__ x, const float* __restrict__ emb,
                             float* __restrict__ out) {
    const int m = blockIdx.x;
    const int tok = x[m];
    const float4* src = (const float4*)(emb + (size_t)tok * EMB_D);
    float4* dst = (float4*)(out + (size_t)m * EMB_D);
    for (int i = threadIdx.x; i < EMB_D / 4; i += blockDim.x) dst[i] = src[i];
}

// ---------------- input projection v3: out[M][N] = A[M][K] @ W[N][K]^T + bias ----
// 256x128 tile, BK=16, 256 threads, 16m x 8n micro-tile, B-side duplication.
__global__ void __launch_bounds__(256, 1)
gemm_xw3_kernel(const float* __restrict__ A, const float* __restrict__ W,
                const float* __restrict__ bih, const float* __restrict__ bhh,
                float* __restrict__ out, int N, int K) {
    extern __shared__ float smg[];
    float* sAs = smg;                    // [2][16][256]
    float* sBs = smg + 2 * 16 * 256;     // [2][16][128]

    const int tid = threadIdx.x;
    const int tm  = tid & 15;
    const int tn  = tid >> 4;
    const int m0  = blockIdx.y * 256;
    const int n0  = blockIdx.x * 128;

    const float* Ap = A + (size_t)(m0 + tid) * K;
    const int fst  = tid ^ ((tid >> 1) & 0x1C);
    const int bn   = tid >> 1;
    const int bkq  = (tid & 1) * 8;
    const float* Wp = W + (size_t)(n0 + bn) * K + bkq;
    const bool bok  = (n0 + bn) < N;

    int aoff[4];
#pragma unroll
    for (int j = 0; j < 4; ++j) {
        const int m = tm * 16 + j * 4;
        aoff[j] = m ^ ((m >> 1) & 0x1C);
    }

    const int NT = K / 16;

    unsigned long long acc[8][8];        // [m-pair][n]
#pragma unroll
    for (int mp = 0; mp < 8; ++mp)
#pragma unroll
        for (int n = 0; n < 8; ++n) acc[mp][n] = 0ull;

    const float4 z4 = make_float4(0.f, 0.f, 0.f, 0.f);
    float4 apf[4], bpf[2];

#pragma unroll
    for (int j = 0; j < 4; ++j) apf[j] = *(const float4*)(Ap + j * 4);
    bpf[0] = bok ? *(const float4*)(Wp)     : z4;
    bpf[1] = bok ? *(const float4*)(Wp + 4) : z4;
    {
        float* sa = sAs;
        float* sb = sBs;
#pragma unroll
        for (int j = 0; j < 4; ++j) {
            sa[(j * 4 + 0) * 256 + fst] = apf[j].x;
            sa[(j * 4 + 1) * 256 + fst] = apf[j].y;
            sa[(j * 4 + 2) * 256 + fst] = apf[j].z;
            sa[(j * 4 + 3) * 256 + fst] = apf[j].w;
        }
        sb[(bkq + 0) * 128 + bn] = bpf[0].x;
        sb[(bkq + 1) * 128 + bn] = bpf[0].y;
        sb[(bkq + 2) * 128 + bn] = bpf[0].z;
        sb[(bkq + 3) * 128 + bn] = bpf[0].w;
        sb[(bkq + 4) * 128 + bn] = bpf[1].x;
        sb[(bkq + 5) * 128 + bn] = bpf[1].y;
        sb[(bkq + 6) * 128 + bn] = bpf[1].z;
        sb[(bkq + 7) * 128 + bn] = bpf[1].w;
    }
    __syncthreads();

    for (int it = 0; it < NT; ++it) {
        const int nxt = it + 1;
        if (nxt < NT) {
            const float* ap2 = Ap + nxt * 16;
#pragma unroll
            for (int j = 0; j < 4; ++j) apf[j] = *(const float4*)(ap2 + j * 4);
            const float* wp2 = Wp + nxt * 16;
            bpf[0] = bok ? *(const float4*)(wp2)     : z4;
            bpf[1] = bok ? *(const float4*)(wp2 + 4) : z4;
        }
        {
            const float* sa = sAs + (it & 1) * (16 * 256);
            const float* sb = sBs + (it & 1) * (16 * 128);
#pragma unroll
            for (int k = 0; k < 16; ++k) {
                unsigned long long ra2[8];
#pragma unroll
                for (int j = 0; j < 4; ++j) {
                    const ulonglong2 q = *(const ulonglong2*)(sa + k * 256 + aoff[j]);
                    ra2[2 * j]     = q.x;
                    ra2[2 * j + 1] = q.y;
                }
                const float4 b0 = *(const float4*)(sb + k * 128 + tn * 8);
                const float4 b1 = *(const float4*)(sb + k * 128 + tn * 8 + 4);
                unsigned long long wb[8];
                wb[0] = pack2(b0.x, b0.x); wb[1] = pack2(b0.y, b0.y);
                wb[2] = pack2(b0.z, b0.z); wb[3] = pack2(b0.w, b0.w);
                wb[4] = pack2(b1.x, b1.x); wb[5] = pack2(b1.y, b1.y);
                wb[6] = pack2(b1.z, b1.z); wb[7] = pack2(b1.w, b1.w);
#pragma unroll
                for (int mp = 0; mp < 8; ++mp)
#pragma unroll
                    for (int n = 0; n < 8; ++n)
                        acc[mp][n] = fma2(ra2[mp], wb[n], acc[mp][n]);
            }
        }
        if (nxt < NT) {
            float* sa = sAs + (nxt & 1) * (16 * 256);
            float* sb = sBs + (nxt & 1) * (16 * 128);
#pragma unroll
            for (int j = 0; j < 4; ++j) {
                sa[(j * 4 + 0) * 256 + fst] = apf[j].x;
                sa[(j * 4 + 1) * 256 + fst] = apf[j].y;
                sa[(j * 4 + 2) * 256 + fst] = apf[j].z;
                sa[(j * 4 + 3) * 256 + fst] = apf[j].w;
            }
            sb[(bkq + 0) * 128 + bn] = bpf[0].x;
            sb[(bkq + 1) * 128 + bn] = bpf[0].y;
            sb[(bkq + 2) * 128 + bn] = bpf[0].z;
            sb[(bkq + 3) * 128 + bn] = bpf[0].w;
            sb[(bkq + 4) * 128 + bn] = bpf[1].x;
            sb[(bkq + 5) * 128 + bn] = bpf[1].y;
            sb[(bkq + 6) * 128 + bn] = bpf[1].z;
            sb[(bkq + 7) * 128 + bn] = bpf[1].w;
        }
        __syncthreads();
    }

    float bias[8];
#pragma unroll
    for (int jj = 0; jj < 8; ++jj) {
        const int n = n0 + tn * 8 + jj;
        bias[jj] = (n < N) ? (__ldg(bih + n) + __ldg(bhh + n)) : 0.0f;
    }
    const bool full = (n0 + 128 <= N);
#pragma unroll
    for (int mp = 0; mp < 8; ++mp) {
        float vlo[8], vhi[8];
#pragma unroll
        for (int n = 0; n < 8; ++n) unpack2(acc[mp][n], vlo[n], vhi[n]);
#pragma unroll
        for (int n = 0; n < 8; ++n) { vlo[n] += bias[n]; vhi[n] += bias[n]; }
        float* orow0 = out + (size_t)(m0 + tm * 16 + 2 * mp) * N + n0 + tn * 8;
        float* orow1 = out + (size_t)(m0 + tm * 16 + 2 * mp + 1) * N + n0 + tn * 8;
        if (full) {
            *(float4*)orow0       = make_float4(vlo[0], vlo[1], vlo[2], vlo[3]);
            *(float4*)(orow0 + 4) = make_float4(vlo[4], vlo[5], vlo[6], vlo[7]);
            *(float4*)orow1       = make_float4(vhi[0], vhi[1], vhi[2], vhi[3]);
            *(float4*)(orow1 + 4) = make_float4(vhi[4], vhi[5], vhi[6], vhi[7]);
        } else {
#pragma unroll
            for (int n = 0; n < 8; ++n)
                if (n0 + tn * 8 + n < N) { orow0[n] = vlo[n]; orow1[n] = vhi[n]; }
        }
    }
}

// ---------------- persistent recurrent LSTM layer (v4, round-11 config) ---------
template <int H>
__global__ void __launch_bounds__(256, 1)
lstm_rec4_kernel(const float* __restrict__ xw, const float* __restrict__ Whh,
                 float* __restrict__ out, int nctas) {
    constexpr int KS    = H / 8;
    constexpr int NCH   = (KS + 15) / 16;
    constexpr int KPADZ = NCH * 16;
    constexpr int WFL   = 8 * KPADZ * 32;

    extern __shared__ float sm[];
    float* sW     = sm;
    float* sStage = sW + WFL;
    float* sC     = sStage;
    float* sCell  = sStage + 16384;

    const int tid  = threadIdx.x;
    const int z    = tid >> 5;
    const int lane = tid & 31;
    const int rgrp = lane & 3;
    const int bg   = lane >> 2;
    const int j0   = blockIdx.x * 8;

    for (int idx = tid; idx < WFL; idx += 256) {
        const int r  = idx & 31;
        const int kl = idx >> 5;
        const int zz = kl / KPADZ;
        const int kp = kl - zz * KPADZ;
        float v = 0.0f;
        if (kp < KS) {
            const int grow = (r >> 3) * H + j0 + (r & 7);
            v = Whh[(size_t)grow * H + zz * KS + kp];
        }
        sW[idx] = v;
    }
    for (int i = tid; i < 512; i += 256) {
        sCell[i] = 0.0f;
        const int u = i & 7, b = i >> 3;
        g_h[0][(j0 + u) * 64 + b] = 0.0f;
    }
    unsigned int ep = 1;
    grid_barrier(nctas, ep * (unsigned)nctas); ++ep;

    const int c0b = tid >> 3, c0u = tid & 7;
    const int c1b = (tid + 256) >> 3, c1u = tid & 7;

    const uint32_t stage_s = (uint32_t)__cvta_generic_to_shared(sStage);
    const float* wbase = sW + z * KPADZ * 32;

    for (int t = 0; t < T_STEPS; ++t) {
        const float* hbuf = g_h[t & 1];
        float* hnext = g_h[1 - (t & 1)];

        float xwv[2][4];
        {
            const float* xb0 = xw + ((size_t)t * 64 + c0b) * (4 * H) + j0 + c0u;
            const float* xb1 = xw + ((size_t)t * 64 + c1b) * (4 * H) + j0 + c1u;
#pragma unroll
            for (int g = 0; g < 4; ++g) {
                xwv[0][g] = __ldg(xb0 + g * H);
                xwv[1][g] = __ldg(xb1 + g * H);
            }
        }

#pragma unroll
        for (int j = 0; j < 8; ++j)
            cpasync16(stage_s + (uint32_t)(j * 256 + tid) * 16,
                      hbuf + (j * KS) * 64 + tid * 4);
        cpcommit();

        unsigned long long acc[4][8];
#pragma unroll
        for (int rp = 0; rp < 4; ++rp)
#pragma unroll
            for (int b = 0; b < 8; ++b) acc[rp][b] = 0ull;

        for (int ci = 0; ci < NCH; ++ci) {
            if (ci + 1 < NCH) {
                const int buf = (ci + 1) & 1;
#pragma unroll
                for (int j = 0; j < 8; ++j)
                    cpasync16(stage_s + (uint32_t)(buf * 2048 + j * 256 + tid) * 16,
                              hbuf + (j * KS + (ci + 1) * 16) * 64 + tid * 4);
                cpcommit();
                asm volatile("cp.async.wait_group 1;" ::: "memory");
            } else {
                asm volatile("cp.async.wait_group 0;" ::: "memory");
            }
            __syncthreads();

            const float4* a4 = (const float4*)sStage + (ci & 1) * 2048 + z * 256;
            const ulonglong2* w2 = (const ulonglong2*)(wbase + ci * 16 * 32) + rgrp * 2;
#pragma unroll
            for (int kk = 0; kk < 16; ++kk) {
                const float4 h01 = a4[kk * 16 + bg * 2];
                const float4 h23 = a4[kk * 16 + bg * 2 + 1];
                const ulonglong2 wA = w2[kk * 8];
                const ulonglong2 wB = w2[kk * 8 + 1];
                const unsigned long long hp0 = pack2(h01.x, h01.x);
                const unsigned long long hp1 = pack2(h01.y, h01.y);
                const unsigned long long hp2 = pack2(h01.z, h01.z);
                const unsigned long long hp3 = pack2(h01.w, h01.w);
                const unsigned long long hp4 = pack2(h23.x, h23.x);
                const unsigned long long hp5 = pack2(h23.y, h23.y);
                const unsigned long long hp6 = pack2(h23.z, h23.z);
                const unsigned long long hp7 = pack2(h23.w, h23.w);
                acc[0][0] = fma2(wA.x, hp0, acc[0][0]);
                acc[1][0] = fma2(wA.y, hp0, acc[1][0]);
                acc[2][0] = fma2(wB.x, hp0, acc[2][0]);
                acc[3][0] = fma2(wB.y, hp0, acc[3][0]);
                acc[0][1] = fma2(wA.x, hp1, acc[0][1]);
                acc[1][1] = fma2(wA.y, hp1, acc[1][1]);
                acc[2][1] = fma2(wB.x, hp1, acc[2][1]);
                acc[3][1] = fma2(wB.y, hp1, acc[3][1]);
                acc[0][2] = fma2(wA.x, hp2, acc[0][2]);
                acc[1][2] = fma2(wA.y, hp2, acc[1][2]);
                acc[2][2] = fma2(wB.x, hp2, acc[2][2]);
                acc[3][2] = fma2(wB.y, hp2, acc[3][2]);
                acc[0][3] = fma2(wA.x, hp3, acc[0][3]);
                acc[1][3] = fma2(wA.y, hp3, acc[1][3]);
                acc[2][3] = fma2(wB.x, hp3, acc[2][3]);
                acc[3][3] = fma2(wB.y, hp3, acc[3][3]);
                acc[0][4] = fma2(wA.x, hp4, acc[0][4]);
                acc[1][4] = fma2(wA.y, hp4, acc[1][4]);
                acc[2][4] = fma2(wB.x, hp4, acc[2][4]);
                acc[3][4] = fma2(wB.y, hp4, acc[3][4]);
                acc[0][5] = fma2(wA.x, hp5, acc[0][5]);
                acc[1][5] = fma2(wA.y, hp5, acc[1][5]);
                acc[2][5] = fma2(wB.x, hp5, acc[2][5]);
                acc[3][5] = fma2(wB.y, hp5, acc[3][5]);
                acc[0][6] = fma2(wA.x, hp6, acc[0][6]);
                acc[1][6] = fma2(wA.y, hp6, acc[1][6]);
                acc[2][6] = fma2(wB.x, hp6, acc[2][6]);
                acc[3][6] = fma2(wB.y, hp6, acc[3][6]);
                acc[0][7] = fma2(wA.x, hp7, acc[0][7]);
                acc[1][7] = fma2(wA.y, hp7, acc[1][7]);
                acc[2][7] = fma2(wB.x, hp7, acc[2][7]);
                acc[3][7] = fma2(wB.y, hp7, acc[3][7]);
            }
        }
        __syncthreads();

#pragma unroll
        for (int b = 0; b < 8; ++b) {
            float* p = sC + z * 2048 + (bg * 8 + b) * 32 + rgrp * 8;
            *(ulonglong2*)p       = make_ulonglong2(acc[0][b], acc[1][b]);
            *(ulonglong2*)(p + 4) = make_ulonglong2(acc[2][b], acc[3][b]);
        }
        __syncthreads();

#pragma unroll
        for (int cc = 0; cc < 2; ++cc) {
            const int b = cc ? c1b : c0b;
            const int u = cc ? c1u : c0u;
            float gsum[4];
#pragma unroll
            for (int g = 0; g < 4; ++g) {
                const int o = b * 32 + g * 8 + u;
                float s = sC[o] + sC[2048 + o];
                s += sC[2 * 2048 + o] + sC[3 * 2048 + o];
                s += sC[4 * 2048 + o] + sC[5 * 2048 + o];
                s += sC[6 * 2048 + o] + sC[7 * 2048 + o];
                gsum[g] = s + xwv[cc][g];
            }
            const int cell = b * 8 + u;
            float c = sCell[cell];
            c = sigm(gsum[1]) * c + sigm(gsum[0]) * tanh_f(gsum[2]);
            sCell[cell] = c;
            const float hv = sigm(gsum[3]) * tanh_f(c);
            hnext[(j0 + u) * 64 + b] = hv;
            out[((size_t)t * 64 + b) * H + j0 + u] = hv;
        }
        grid_barrier(nctas, ep * (unsigned)nctas); ++ep;
    }
}

// ---------------- layer-2 recurrence: NJ=4, H=400 -> 100 CTAs (round-11) --------
__global__ void __launch_bounds__(256, 1)
lstm_l2_kernel(const float* __restrict__ xw, const float* __restrict__ Whh,
               float* __restrict__ out, int nctas) {
    constexpr int H     = EMB_D;       // 400
    constexpr int KS    = H / 8;       // 50
    constexpr int NCH   = 4;           // ceil(50/16)
    constexpr int KPADZ = 64;
    constexpr int WFL   = 8 * KPADZ * 16;   // 8192 floats

    extern __shared__ float sm[];
    float* sW     = sm;                     // [8 z][64 kp][16 r]
    float* sStage = sW + WFL;               // [2][2048 float4] = 16384 fl
    float* sC     = sStage;                 // alias: [8 z][64 b][16 r]
    float* sCell  = sStage + 16384;         // [256]

    const int tid  = threadIdx.x;
    const int z    = tid >> 5;
    const int lane = tid & 31;
    const int rgrp = lane & 1;
    const int bg   = lane >> 1;
    const int j0   = blockIdx.x * 4;

    for (int idx = tid; idx < WFL; idx += 256) {
        const int r  = idx & 15;
        const int kl = idx >> 4;
        const int zz = kl >> 6;
        const int kp = kl & 63;
        float v = 0.0f;
        if (kp < KS) {
            const int grow = (r >> 2) * H + j0 + (r & 3);
            v = Whh[(size_t)grow * H + zz * KS + kp];
        }
        sW[idx] = v;
    }
    for (int i = tid; i < 256; i += 256) {
        sCell[i] = 0.0f;
        const int u = i & 3, b = i >> 2;
        g_h[0][(j0 + u) * 64 + b] = 0.0f;
    }
    unsigned int ep = 1;
    grid_barrier(nctas, ep * (unsigned)nctas); ++ep;

    const int c0b = tid >> 2, c0u = tid & 3;

    const uint32_t stage_s = (uint32_t)__cvta_generic_to_shared(sStage);
    const float* wbase = sW + z * KPADZ * 16;

    for (int t = 0; t < T_STEPS; ++t) {
        const float* hbuf = g_h[t & 1];
        float* hnext = g_h[1 - (t & 1)];

        float xwv[4];
        {
            const float* xb0 = xw + ((size_t)t * 64 + c0b) * (4 * H) + j0 + c0u;
#pragma unroll
            for (int g = 0; g < 4; ++g) xwv[g] = __ldg(xb0 + g * H);
        }

#pragma unroll
        for (int j = 0; j < 8; ++j)
            cpasync16(stage_s + (uint32_t)(j * 256 + tid) * 16,
                      hbuf + (j * KS) * 64 + tid * 4);
        cpcommit();

        unsigned long long acc[4][4];
#pragma unroll
        for (int rp = 0; rp < 4; ++rp)
#pragma unroll
            for (int b = 0; b < 4; ++b) acc[rp][b] = 0ull;

        for (int ci = 0; ci < NCH; ++ci) {
            if (ci + 1 < NCH) {
                const int buf = (ci + 1) & 1;
#pragma unroll
                for (int j = 0; j < 8; ++j)
                    cpasync16(stage_s + (uint32_t)(buf * 2048 + j * 256 + tid) * 16,
                              hbuf + (j * KS + (ci + 1) * 16) * 64 + tid * 4);
                cpcommit();
                asm volatile("cp.async.wait_group 1;" ::: "memory");
            } else {
                asm volatile("cp.async.wait_group 0;" ::: "memory");
            }
            __syncthreads();

            const float4* a4 = (const float4*)sStage + (ci & 1) * 2048 + z * 256;
            const ulonglong2* w2 = (const ulonglong2*)(wbase + ci * 16 * 16) + rgrp * 2;
#pragma unroll
            for (int kk = 0; kk < 16; ++kk) {
                const float4 hq = a4[kk * 16 + bg];
                const ulonglong2 wA = w2[kk * 4];
                const ulonglong2 wB = w2[kk * 4 + 1];
                const unsigned long long hp0 = pack2(hq.x, hq.x);
                const unsigned long long hp1 = pack2(hq.y, hq.y);
                const unsigned long long hp2 = pack2(hq.z, hq.z);
                const unsigned long long hp3 = pack2(hq.w, hq.w);
                acc[0][0] = fma2(wA.x, hp0, acc[0][0]);
                acc[1][0] = fma2(wA.y, hp0, acc[1][0]);
                acc[2][0] = fma2(wB.x, hp0, acc[2][0]);
                acc[3][0] = fma2(wB.y, hp0, acc[3][0]);
                acc[0][1] = fma2(wA.x, hp1, acc[0][1]);
                acc[1][1] = fma2(wA.y, hp1, acc[1][1]);
                acc[2][1] = fma2(wB.x, hp1, acc[2][1]);
                acc[3][1] = fma2(wB.y, hp1, acc[3][1]);
                acc[0][2] = fma2(wA.x, hp2, acc[0][2]);
                acc[1][2] = fma2(wA.y, hp2, acc[1][2]);
                acc[2][2] = fma2(wB.x, hp2, acc[2][2]);
                acc[3][2] = fma2(wB.y, hp2, acc[3][2]);
                acc[0][3] = fma2(wA.x, hp3, acc[0][3]);
                acc[1][3] = fma2(wA.y, hp3, acc[1][3]);
                acc[2][3] = fma2(wB.x, hp3, acc[2][3]);
                acc[3][3] = fma2(wB.y, hp3, acc[3][3]);
            }
        }
        __syncthreads();

#pragma unroll
        for (int b = 0; b < 4; ++b) {
            float* p = sC + z * 1024 + (bg * 4 + b) * 16 + rgrp * 8;
            *(ulonglong2*)p       = make_ulonglong2(acc[0][b], acc[1][b]);
            *(ulonglong2*)(p + 4) = make_ulonglong2(acc[2][b], acc[3][b]);
        }
        __syncthreads();

        {
            const int b = c0b, u = c0u;
            float gsum[4];
#pragma unroll
            for (int g = 0; g < 4; ++g) {
                const int o = b * 16 + g * 4 + u;
                float s = sC[o] + sC[1024 + o];
                s += sC[2 * 1024 + o] + sC[3 * 1024 + o];
                s += sC[4 * 1024 + o] + sC[5 * 1024 + o];
                s += sC[6 * 1024 + o] + sC[7 * 1024 + o];
                gsum[g] = s + xwv[g];
            }
            float c = sCell[tid];
            c = sigm(gsum[1]) * c + sigm(gsum[0]) * tanh_f(gsum[2]);
            sCell[tid] = c;
            const float hv = sigm(gsum[3]) * tanh_f(c);
            hnext[(j0 + u) * 64 + b] = hv;
            out[((size_t)t * 64 + b) * H + j0 + u] = hv;
        }
        grid_barrier(nctas, ep * (unsigned)nctas); ++ep;
    }
}

// ---------------- launch ----------------
extern "C" void kernel_launch(void* const* d_in, const int* in_sizes, int n_in,
                              void* d_out, int out_size) {
    (void)in_sizes; (void)n_in; (void)out_size;
    const int*   x    = (const int*)d_in[0];
    const float* emb  = (const float*)d_in[1];
    const float* Wih0 = (const float*)d_in[2];
    const float* Whh0 = (const float*)d_in[3];
    const float* bih0 = (const float*)d_in[4];
    const float* bhh0 = (const float*)d_in[5];
    const float* Wih1 = (const float*)d_in[6];
    const float* Whh1 = (const float*)d_in[7];
    const float* bih1 = (const float*)d_in[8];
    const float* bhh1 = (const float*)d_in[9];
    const float* Wih2 = (const float*)d_in[10];
    const float* Whh2 = (const float*)d_in[11];
    const float* bih2 = (const float*)d_in[12];
    const float* bhh2 = (const float*)d_in[13];
    float* out = (float*)d_out;

    float *act0, *act1, *xw;
    cudaGetSymbolAddress((void**)&act0, g_act0);
    cudaGetSymbolAddress((void**)&act1, g_act1);
    cudaGetSymbolAddress((void**)&xw, g_xw);

    const size_t SMEM_GEMM = (size_t)(2 * 16 * 256 + 2 * 16 * 128) * sizeof(float); // 49152
    const size_t SMEM_BIG  = (size_t)(8 * 144 * 32 + 16384 + 512) * sizeof(float);  // 215040
    const size_t SMEM_L2   = (size_t)(8 * 64 * 16 + 16384 + 256) * sizeof(float);   // 99328
    cudaFuncSetAttribute((const void*)gemm_xw3_kernel,
                         cudaFuncAttributeMaxDynamicSharedMemorySize, (int)SMEM_GEMM);
    cudaFuncSetAttribute((const void*)lstm_rec4_kernel<HID_D>,
                         cudaFuncAttributeMaxDynamicSharedMemorySize, (int)SMEM_BIG);
    cudaFuncSetAttribute((const void*)lstm_l2_kernel,
                         cudaFuncAttributeMaxDynamicSharedMemorySize, (int)SMEM_L2);

    // embedding
    embed_kernel<<<M_ROWS, 128>>>(x, emb, act0);

    // layer 0: din=400, H=1152
    gemm_xw3_kernel<<<dim3(36, 128), 256, SMEM_GEMM>>>(act0, Wih0, bih0, bhh0, xw, 4 * HID_D, EMB_D);
    reset_bar_kernel<<<1, 1>>>();
    lstm_rec4_kernel<HID_D><<<144, 256, SMEM_BIG>>>(xw, Whh0, act1, 144);

    // layer 1: din=1152, H=1152
    gemm_xw3_kernel<<<dim3(36, 128), 256, SMEM_GEMM>>>(act1, Wih1, bih1, bhh1, xw, 4 * HID_D, HID_D);
    reset_bar_kernel<<<1, 1>>>();
    lstm_rec4_kernel<HID_D><<<144, 256, SMEM_BIG>>>(xw, Whh1, act0, 144);

    // layer 2: din=1152, H=400 (100 CTAs, NJ=4)
    gemm_xw3_kernel<<<dim3(13, 128), 256, SMEM_GEMM>>>(act0, Wih2, bih2, bhh2, xw, 4 * EMB_D, HID_D);
    reset_bar_kernel<<<1, 1>>>();
    lstm_l2_kernel<<<100, 256, SMEM_L2>>>(xw, Whh2, out, 100);
}